// round 13
// baseline (speedup 1.0000x reference)
#include <cuda_runtime.h>

#define N 4096
#define NN (1u << 24)  // 4096*4096

// Scratch (no device allocation allowed). 16B-aligned so float4 loads are legal.
__device__ __align__(16) float g_z0r[N];
__device__ __align__(16) float g_z0i[N];
__device__ __align__(16) float g_x0r[N];
__device__ __align__(16) float g_x0i[N];

// Kernel 0: gather column 0 of z and x. ONE load per thread (16384 threads,
// 128 CTAs x 128) so every scattered sector fetch is independent and the
// kernel is a single DRAM-latency deep. Triggers dependent launch ASAP (PDL).
__global__ void gather_vec_kernel(const float* __restrict__ xr,
                                  const float* __restrict__ xi,
                                  const float* __restrict__ zr,
                                  const float* __restrict__ zi) {
    int g = blockIdx.x * 128 + threadIdx.x;   // 0 .. 16383
    int row = g & (N - 1);
    int which = g >> 12;                      // warp-uniform (128 warps per array)
    const float* src = (which == 0) ? zr : (which == 1) ? zi
                     : (which == 2) ? xr : xi;
    float* dst = (which == 0) ? g_z0r : (which == 1) ? g_z0i
               : (which == 2) ? g_x0r : g_x0i;
    dst[row] = src[(size_t)row * N];
#if __CUDA_ARCH__ >= 900
    cudaTriggerProgrammaticLaunchCompletion();
#endif
}

// Fused kernel: one CTA per row m. (R8 body + PDL prologue + SW pipeline.)
// Phase 1: Re(z_i)[m] = 0.5*(Ar[m,:]@z0r - Ai[m,:]@z0i + Br[m,:]@x0r - Bi[m,:]@x0i)
//   First batch of matrix loads issued BEFORE cudaGridDependencySynchronize()
//   (they don't depend on the gather), hiding gather + launch latency.
// Phase 2: row-m epilogue, float4-vectorized.
// Output layout: out = [ y_t.real (NN) | z_j.real (NN) ].
__global__ __launch_bounds__(256, 6) void fused_kernel(const float* __restrict__ Ar,
                                                       const float* __restrict__ Ai,
                                                       const float* __restrict__ Br,
                                                       const float* __restrict__ Bi,
                                                       const float* __restrict__ zr,
                                                       float* __restrict__ out) {
    const int m = blockIdx.x;
    const size_t base = (size_t)m * N;

    const float4* ar4 = (const float4*)(Ar + base);
    const float4* ai4 = (const float4*)(Ai + base);
    const float4* br4 = (const float4*)(Br + base);
    const float4* bi4 = (const float4*)(Bi + base);
    const float4* vzr4 = (const float4*)g_z0r;
    const float4* vzi4 = (const float4*)g_z0i;
    const float4* vxr4 = (const float4*)g_x0r;
    const float4* vxi4 = (const float4*)g_x0i;

    // Prologue: prefetch iteration 0's matrix data (independent of gather).
    int k = threadIdx.x;
    float4 a_r = __ldcs(ar4 + k);
    float4 a_i = __ldcs(ai4 + k);
    float4 b_r = __ldcs(br4 + k);
    float4 b_i = __ldcs(bi4 + k);

#if __CUDA_ARCH__ >= 900
    cudaGridDependencySynchronize();   // gather results visible after this
#endif

    float sr = 0.f;
    while (true) {
        float4 vz_r = vzr4[k];          // L1-resident working set
        float4 vz_i = vzi4[k];
        float4 vx_r = vxr4[k];
        float4 vx_i = vxi4[k];

        sr += a_r.x * vz_r.x - a_i.x * vz_i.x + b_r.x * vx_r.x - b_i.x * vx_i.x;
        sr += a_r.y * vz_r.y - a_i.y * vz_i.y + b_r.y * vx_r.y - b_i.y * vx_i.y;
        sr += a_r.z * vz_r.z - a_i.z * vz_i.z + b_r.z * vx_r.z - b_i.z * vx_i.z;
        sr += a_r.w * vz_r.w - a_i.w * vz_i.w + b_r.w * vx_r.w - b_i.w * vx_i.w;

        k += 256;
        if (k >= N / 4) break;
        a_r = __ldcs(ar4 + k);          // software pipeline: next iter's loads
        a_i = __ldcs(ai4 + k);
        b_r = __ldcs(br4 + k);
        b_i = __ldcs(bi4 + k);
    }

    for (int off = 16; off > 0; off >>= 1)
        sr += __shfl_down_sync(0xffffffffu, sr, off);

    __shared__ float red[8];
    __shared__ float s_zir;
    int lane = threadIdx.x & 31;
    int wid = threadIdx.x >> 5;
    if (lane == 0) red[wid] = sr;
    __syncthreads();
    if (threadIdx.x == 0) {
        float tr = 0.f;
        #pragma unroll
        for (int w = 0; w < 8; w++) tr += red[w];
        s_zir = 0.5f * tr;
    }
    __syncthreads();
    const float zvr = s_zir;

    // Phase 2: float4 epilogue over this row's 4096 columns (1024 float4).
    const float4* zrow4 = (const float4*)(zr + base);
    const float* zrow = zr + base;
    float4* outy4 = (float4*)out + (size_t)m * (N / 4);
    float4* outj4 = (float4*)out + (size_t)(NN / 4) + (size_t)m * (N / 4);

    #pragma unroll 4
    for (int t = threadIdx.x; t < N / 4; t += 256) {
        float4 v = zrow4[t];                       // cols 4t .. 4t+3
        int c_next = 4 * t + 4;
        float nxt = (c_next < N) ? zrow[c_next] : zvr;  // L1 hit

        float4 j = make_float4(v.y, v.z, v.w, nxt);
        float4 y = make_float4(zvr + j.x, zvr + j.y, zvr + j.z, zvr + j.w);

        __stcs(outy4 + t, y);
        __stcs(outj4 + t, j);
    }
}

extern "C" void kernel_launch(void* const* d_in, const int* in_sizes, int n_in,
                              void* d_out, int out_size) {
    const float* xr = (const float*)d_in[0];
    const float* xi = (const float*)d_in[1];
    const float* zr = (const float*)d_in[2];
    const float* zi = (const float*)d_in[3];
    const float* Ar = (const float*)d_in[4];
    const float* Ai = (const float*)d_in[5];
    const float* Br = (const float*)d_in[6];
    const float* Bi = (const float*)d_in[7];
    float* out = (float*)d_out;

    gather_vec_kernel<<<128, 128>>>(xr, xi, zr, zi);

    // Launch fused kernel with Programmatic Dependent Launch so it overlaps
    // the gather's execution; fall back to a plain launch if unsupported.
    cudaLaunchConfig_t cfg = {};
    cfg.gridDim = dim3(N, 1, 1);
    cfg.blockDim = dim3(256, 1, 1);
    cfg.dynamicSmemBytes = 0;
    cfg.stream = 0;
    cudaLaunchAttribute attr[1];
    attr[0].id = cudaLaunchAttributeProgrammaticStreamSerialization;
    attr[0].val.programmaticStreamSerializationAllowed = 1;
    cfg.attrs = attr;
    cfg.numAttrs = 1;

    cudaError_t e = cudaLaunchKernelEx(&cfg, fused_kernel,
                                       Ar, Ai, Br, Bi, zr, out);
    if (e != cudaSuccess) {
        (void)cudaGetLastError();  // clear
        fused_kernel<<<N, 256>>>(Ar, Ai, Br, Bi, zr, out);
    }
}

// round 14
// speedup vs baseline: 1.0123x; 1.0123x over previous
#include <cuda_runtime.h>

#define N 4096
#define NN (1u << 24)  // 4096*4096

// Scratch (no device allocation allowed). 16B-aligned so float4 loads are legal.
__device__ __align__(16) float g_z0r[N];
__device__ __align__(16) float g_z0i[N];
__device__ __align__(16) float g_x0r[N];
__device__ __align__(16) float g_x0i[N];

// Kernel 0: gather column 0 of z and x. ONE load per thread (16384 threads,
// 128 CTAs x 128) so every scattered sector fetch is independent and the
// kernel is a single DRAM-latency deep. Triggers dependent launch ASAP (PDL).
__global__ void gather_vec_kernel(const float* __restrict__ xr,
                                  const float* __restrict__ xi,
                                  const float* __restrict__ zr,
                                  const float* __restrict__ zi) {
    int g = blockIdx.x * 128 + threadIdx.x;   // 0 .. 16383
    int row = g & (N - 1);
    int which = g >> 12;                      // warp-uniform (128 warps per array)
    const float* src = (which == 0) ? zr : (which == 1) ? zi
                     : (which == 2) ? xr : xi;
    float* dst = (which == 0) ? g_z0r : (which == 1) ? g_z0i
               : (which == 2) ? g_x0r : g_x0i;
    dst[row] = src[(size_t)row * N];
#if __CUDA_ARCH__ >= 900
    cudaTriggerProgrammaticLaunchCompletion();
#endif
}

// Fused kernel: one CTA per row m.  EXACT Round-10 body (best measured:
// 70.6us, DRAM 74%) with only a PDL grid-dependency sync added at entry.
// R13's manual software pipeline regressed (ALU 1.5->8.1%) — ptxas batches
// the loads better itself under #pragma unroll 4.
// Phase 1: Re(z_i)[m] = 0.5*(Ar[m,:]@z0r - Ai[m,:]@z0i + Br[m,:]@x0r - Bi[m,:]@x0i)
// Phase 2: row-m epilogue, float4-vectorized.
// Output layout: out = [ y_t.real (NN) | z_j.real (NN) ].
__global__ __launch_bounds__(256, 6) void fused_kernel(const float* __restrict__ Ar,
                                                       const float* __restrict__ Ai,
                                                       const float* __restrict__ Br,
                                                       const float* __restrict__ Bi,
                                                       const float* __restrict__ zr,
                                                       float* __restrict__ out) {
#if __CUDA_ARCH__ >= 900
    cudaGridDependencySynchronize();   // gather results visible after this
#endif

    const int m = blockIdx.x;
    const size_t base = (size_t)m * N;

    const float4* ar4 = (const float4*)(Ar + base);
    const float4* ai4 = (const float4*)(Ai + base);
    const float4* br4 = (const float4*)(Br + base);
    const float4* bi4 = (const float4*)(Bi + base);
    const float4* vzr4 = (const float4*)g_z0r;
    const float4* vzi4 = (const float4*)g_z0i;
    const float4* vxr4 = (const float4*)g_x0r;
    const float4* vxi4 = (const float4*)g_x0i;

    float sr = 0.f;
    #pragma unroll 4
    for (int k = threadIdx.x; k < N / 4; k += 256) {
        float4 a_r = __ldcs(ar4 + k);   // streaming: evict-first
        float4 a_i = __ldcs(ai4 + k);
        float4 b_r = __ldcs(br4 + k);
        float4 b_i = __ldcs(bi4 + k);
        float4 vz_r = vzr4[k];          // L1-resident working set
        float4 vz_i = vzi4[k];
        float4 vx_r = vxr4[k];
        float4 vx_i = vxi4[k];

        sr += a_r.x * vz_r.x - a_i.x * vz_i.x + b_r.x * vx_r.x - b_i.x * vx_i.x;
        sr += a_r.y * vz_r.y - a_i.y * vz_i.y + b_r.y * vx_r.y - b_i.y * vx_i.y;
        sr += a_r.z * vz_r.z - a_i.z * vz_i.z + b_r.z * vx_r.z - b_i.z * vx_i.z;
        sr += a_r.w * vz_r.w - a_i.w * vz_i.w + b_r.w * vx_r.w - b_i.w * vx_i.w;
    }

    for (int off = 16; off > 0; off >>= 1)
        sr += __shfl_down_sync(0xffffffffu, sr, off);

    __shared__ float red[8];
    __shared__ float s_zir;
    int lane = threadIdx.x & 31;
    int wid = threadIdx.x >> 5;
    if (lane == 0) red[wid] = sr;
    __syncthreads();
    if (threadIdx.x == 0) {
        float tr = 0.f;
        #pragma unroll
        for (int w = 0; w < 8; w++) tr += red[w];
        s_zir = 0.5f * tr;
    }
    __syncthreads();
    const float zvr = s_zir;

    // Phase 2: float4 epilogue over this row's 4096 columns (1024 float4).
    const float4* zrow4 = (const float4*)(zr + base);
    const float* zrow = zr + base;
    float4* outy4 = (float4*)out + (size_t)m * (N / 4);
    float4* outj4 = (float4*)out + (size_t)(NN / 4) + (size_t)m * (N / 4);

    #pragma unroll 4
    for (int t = threadIdx.x; t < N / 4; t += 256) {
        float4 v = zrow4[t];                       // cols 4t .. 4t+3
        int c_next = 4 * t + 4;
        float nxt = (c_next < N) ? zrow[c_next] : zvr;  // L1 hit

        float4 j = make_float4(v.y, v.z, v.w, nxt);
        float4 y = make_float4(zvr + j.x, zvr + j.y, zvr + j.z, zvr + j.w);

        __stcs(outy4 + t, y);
        __stcs(outj4 + t, j);
    }
}

extern "C" void kernel_launch(void* const* d_in, const int* in_sizes, int n_in,
                              void* d_out, int out_size) {
    const float* xr = (const float*)d_in[0];
    const float* xi = (const float*)d_in[1];
    const float* zr = (const float*)d_in[2];
    const float* zi = (const float*)d_in[3];
    const float* Ar = (const float*)d_in[4];
    const float* Ai = (const float*)d_in[5];
    const float* Br = (const float*)d_in[6];
    const float* Bi = (const float*)d_in[7];
    float* out = (float*)d_out;

    gather_vec_kernel<<<128, 128>>>(xr, xi, zr, zi);

    // Launch fused kernel with Programmatic Dependent Launch so it overlaps
    // the gather's execution; fall back to a plain launch if unsupported.
    cudaLaunchConfig_t cfg = {};
    cfg.gridDim = dim3(N, 1, 1);
    cfg.blockDim = dim3(256, 1, 1);
    cfg.dynamicSmemBytes = 0;
    cfg.stream = 0;
    cudaLaunchAttribute attr[1];
    attr[0].id = cudaLaunchAttributeProgrammaticStreamSerialization;
    attr[0].val.programmaticStreamSerializationAllowed = 1;
    cfg.attrs = attr;
    cfg.numAttrs = 1;

    cudaError_t e = cudaLaunchKernelEx(&cfg, fused_kernel,
                                       Ar, Ai, Br, Bi, zr, out);
    if (e != cudaSuccess) {
        (void)cudaGetLastError();  // clear
        fused_kernel<<<N, 256>>>(Ar, Ai, Br, Bi, zr, out);
    }
}